// round 12
// baseline (speedup 1.0000x reference)
#include <cuda_runtime.h>
#include <stdint.h>

// samx_qkv_1bit: suffix-automaton retrieval, 1024 independent serial rows.
// R12 = R11 (uniform warp-cooperative step, records reloaded per step) +
//  - plants/redirects as STS.32 low-word (tr bits only) -> no byte overlap
//    with STS.16 r-stores -> r-propagation merged into ONE store phase,
//    3 syncwarps/step -> 2
//  - speculative dual-tgt (clone/non-clone) computed in parallel ballots;
//    S[d] load taken off the keepm critical path
//  - query first-node record preloaded with the other step-top loads
// smem/block: 229376 (records) + 1792 (vpk) + 476 (NCid) = 231644 <= 232448.

#define BB 4
#define TT 2048
#define CC 256
#define NROWS (BB*CC)          // 1024
#define WPB (TT/32)            // 64 packed words per row
#define STATES 4096            // SAM has <= 2n-1 = 4095 states
#define RPB 7                  // rows (warps) per block
#define CAPC 34                // NCid slots per warp

typedef unsigned long long ull;
#define IDA 0xFFF              // 12-bit absent / -1 marker
#define F_SH 24
#define M_SH 36
#define R_SH 48
#define FULLM 0xFFFFFFFFu
#define RMASK (0xFFFFull << R_SH)
#define MMASK ((ull)IDA << M_SH)
#define FMASK ((ull)IDA << F_SH)

__device__ uint32_t g_qpack[NROWS*WPB];
__device__ uint32_t g_kpack[NROWS*WPB];
__device__ uint32_t g_vpack[NROWS*WPB];

// ---------------------------------------------------------------------------
__global__ void samx_pack_kernel(const float* __restrict__ q,
                                 const float* __restrict__ k,
                                 const float* __restrict__ v) {
    int c  = threadIdx.x;
    int wi = blockIdx.x;
    int b  = blockIdx.y;
    int row = b * CC + c;
    size_t base = ((size_t)b * TT + (size_t)wi * 32) * CC + c;
    uint32_t qw = 0, kw = 0, vw = 0;
#pragma unroll
    for (int s = 0; s < 32; s++) {
        if (q[base + (size_t)s * CC] > 0.f) qw |= 1u << s;
        if (k[base + (size_t)s * CC] > 0.f) kw |= 1u << s;
        if (v[base + (size_t)s * CC] > 0.f) vw |= 1u << s;
    }
    g_qpack[row * WPB + wi] = qw;
    g_kpack[row * WPB + wi] = kw;
    g_vpack[row * WPB + wi] = vw;
}

// ---------------------------------------------------------------------------
extern "C" __global__ void __launch_bounds__(32*RPB, 1)
samx_sam_kernel(const float* __restrict__ e, float* __restrict__ out) {
    extern __shared__ ull smem[];
    int warp = threadIdx.x >> 5;
    int lane = threadIdx.x & 31;
    int row  = blockIdx.x * RPB + warp;

    ull* S = smem + (size_t)warp * STATES;
    uint32_t* S32 = (uint32_t*)S;                         // low word = idx 2n
    unsigned short* Sr = (unsigned short*)S;              // r+1 halfword = idx 4n+3
    uint32_t* vpk_s = (uint32_t*)(smem + (size_t)RPB * STATES) + warp * WPB;
    unsigned short* NC = (unsigned short*)((char*)smem
                       + (size_t)RPB * STATES * sizeof(ull)
                       + (size_t)RPB * WPB * sizeof(uint32_t))
                       + warp * CAPC;

    if (row < NROWS) {
        vpk_s[lane]      = g_vpack[row * WPB + lane];
        vpk_s[lane + 32] = g_vpack[row * WPB + lane + 32];
    }
    __syncwarp();
    if (row >= NROWS) return;

    const uint32_t* qpk = g_qpack + row * WPB;
    const uint32_t* kpk = g_kpack + row * WPB;

    int b = row >> 8;
    int c = row & (CC - 1);
    float ev = e[c];
    float* op = out + (size_t)b * TT * CC + c;

    // ---- bootstrap: step i=0 inline ----
    uint32_t qw, kw;
    { uint32_t a = 0, b2 = 0;
      if (lane == 0) { a = qpk[0]; b2 = kpk[0]; }
      qw = __shfl_sync(FULLM, a, 0); kw = __shfl_sync(FULLM, b2, 0); }
    int k0 = (kw & 1) ? 12 : 0;
    ull rootP = ((ull)IDA | ((ull)IDA << 12) | ((ull)IDA << F_SH));
    rootP = (rootP & ~((ull)IDA << k0)) | ((ull)1 << k0);   // tk[root]=1
    ull n1 = (ull)IDA | ((ull)IDA << 12) | ((ull)1 << M_SH) | ((ull)1 << R_SH);
    if (lane == 0) {
        S[0] = rootP; S[1] = n1;
        NC[0] = 1; NC[1] = 0;
        op[0] = -ev;                                        // query(0): y=0
    }
    int L = 2, g = 1, u = 2, w = 0, h = 0;
    bool degraded = false;
    __syncwarp();

    for (int i = 1; i < TT; i++) {
        if ((i & 31) == 0) {
            uint32_t a = 0, b2 = 0;
            if (lane == 0) { int wi = i >> 5; a = qpk[wi]; b2 = kpk[wi]; }
            qw = __shfl_sync(FULLM, a, 0); kw = __shfl_sync(FULLM, b2, 0);
        }
        int qs = ((qw >> (i & 31)) & 1) ? 12 : 0;
        int ks = ((kw >> (i & 31)) & 1) ? 12 : 0;
        int j = u;
        ull rvR = ((ull)(i + 1)) << R_SH;
        unsigned short rv = (unsigned short)(i + 1);

        if (!degraded) {
            // ---- preloads (issue together) ----
            int idt = (int)NC[lane] & IDA;
            ull rec  = S[idt];
            ull recq = S[w];                              // query first node
            bool validt = (lane < L);
            int tkt = validt ? (int)((rec >> ks) & IDA) : IDA;
            int mpt = (int)((rec >> M_SH) & IDA);
            ull planted = (rec & ~((ull)IDA << ks)) | ((ull)j << ks);

            // ---- collective chain (speculative dual-tgt) ----
            unsigned pres = __ballot_sync(FULLM, tkt != IDA);
            int s = pres ? (__ffs(pres) - 1) : L;
            int d  = __shfl_sync(FULLM, tkt, s & 31);
            int mp = __shfl_sync(FULLM, mpt, s & 31);
            bool hitd = validt && (tkt == d);
            bool inrun = (lane > s) && hitd;
            int bc = j + 1;
            int tgt_nc = tkt;                             // lane s: == d == fj_nc
            int tgt_cl = inrun ? bc : tkt;
            if (lane == s) tgt_cl = bc;                   // fj_cl
            int pnc = __shfl_up_sync(FULLM, tgt_nc, 1);
            int pcl = __shfl_up_sync(FULLM, tgt_cl, 1);
            bool rng = validt && (lane > s);
            unsigned km_nc = __ballot_sync(FULLM, rng && (tgt_nc != pnc));
            unsigned km_cl = __ballot_sync(FULLM, rng && (tgt_cl != pcl));
            // recd path (resolves concurrently with the tgt ballots)
            unsigned dch = __ballot_sync(FULLM, validt && (lane < s) && (idt == d));
            bool donchain = pres && (dch != 0);
            int dlane = (__ffs(dch) - 1) & 31;
            ull recd_l = S[pres ? d : 0];
            ull plsh = __shfl_sync(FULLM, planted, dlane);
            ull recd = donchain ? plsh : recd_l;
            int md = (int)((recd >> M_SH) & IDA);
            bool clone = pres && (mp + 1 != md);
            int fj = pres ? (clone ? bc : d) : 0;
            unsigned keepm = clone ? km_cl : km_nc;
            int tgt = clone ? tgt_cl : tgt_nc;
            int nk = __popc(keepm);
            bool keep = (keepm >> lane) & 1u;
            int pos = 2 + __popc(keepm & ((1u << lane) - 1u));
            int Lnext = pres ? nk + 3 : 2;
            ull jrec = (ull)IDA | ((ull)IDA << 12) | ((ull)fj << F_SH)
                     | ((ull)(i + 1) << M_SH) | rvR;
            ull fjrec = (recd & ~(MMASK | RMASK))
                      | ((ull)(mp + 1) << M_SH) | rvR;    // used iff clone

            // ---- query (uniform on ALL lanes; first record preloaded) ----
            {
                int p = w, x = h;
                ull r2 = recq;
                for (;;) {
                    int tq = (int)((r2 >> qs) & IDA);
                    if (tq != IDA) { p = tq; x += 1; break; }
                    int mq = (int)((r2 >> M_SH) & IDA);
                    if (x > mq) x = mq;
                    int f = (int)((r2 >> F_SH) & IDA);
                    if (f == IDA) { p = 0; x = 0; break; }
                    p = f;
                    r2 = S[p];
                }
                int y = 0;
                if (x > 0) {
                    ull recv = S[p];
                    for (;;) {
                        int f = (int)((recv >> F_SH) & IDA);
                        if (f == IDA) break;
                        ull recf = S[f];
                        if ((int)((recf >> M_SH) & IDA) >= x) recv = recf;
                        else break;
                    }
                    int idx = (int)(recv >> R_SH);        // r+1
                    y = (int)((vpk_s[idx >> 5] >> (idx & 31)) & 1u);
                }
                if (lane == 0) op[(size_t)i * CC] = y ? ev : -ev;
                w = p; h = x;
            }
            __syncwarp();   // S1: all S reads complete

            // ---- single merged store phase ----
            if (lane < s) {                               // plants (tr bits only)
                if (donchain && lane == dlane) {
                    ull pl = planted;
                    if (clone) pl = (pl & ~FMASK) | ((ull)bc << F_SH);  // f[d]=bc
                    else       pl = (pl & ~RMASK) | rvR;                // r[d]=rv
                    S[idt] = pl;
                } else {
                    S32[idt << 1] = (uint32_t)planted;    // STS.32 low word
                }
            }
            if (pres && lane == s) {
                if (clone) {
                    S32[idt << 1] = (uint32_t)
                        ((rec & ~((ull)IDA << ks)) | ((ull)bc << ks));
                    S[bc] = fjrec;
                    if (!donchain) S[d] = (recd & ~FMASK) | ((ull)bc << F_SH);
                } else if (!donchain) {
                    Sr[(d << 2) | 3] = rv;
                }
            }
            if (clone && inrun)
                S32[idt << 1] = (uint32_t)
                    ((rec & ~((ull)IDA << ks)) | ((ull)bc << ks));
            if (rng) Sr[(tgt << 2) | 3] = rv;             // merged r-propagation
            if (lane == 0) {
                S[j] = jrec;
                NC[0] = (unsigned short)j;
                NC[1] = (unsigned short)fj;
                NC[Lnext - 1] = 0;                        // root terminal
            }
            if (keep) NC[pos] = (unsigned short)tgt;
            __syncwarp();   // S2: all writes visible to next step

            g = j; u += clone ? 2 : 1; L = Lnext;
            if (L > 32) degraded = true;   // S coherent; fallback takes over
        } else {
            // ---- serial fallback: lane 0, reference-style (always correct) ----
            if (lane == 0) {
                // query
                int p = w, x = h;
                for (;;) {
                    if (p < 0) { p = 0; x = 0; break; }
                    ull r2 = S[p];
                    int tq = (int)((r2 >> qs) & IDA);
                    if (tq != IDA) { p = tq; x += 1; break; }
                    int mq = (int)((r2 >> M_SH) & IDA);
                    if (x > mq) x = mq;
                    int f = (int)((r2 >> F_SH) & IDA);
                    p = (f == IDA) ? -1 : f;
                }
                int y = 0;
                if (x > 0) {
                    ull recv = S[p];
                    for (;;) {
                        int f = (int)((recv >> F_SH) & IDA);
                        if (f == IDA) break;
                        ull recf = S[f];
                        if ((int)((recf >> M_SH) & IDA) >= x) recv = recf;
                        else break;
                    }
                    int idx = (int)(recv >> R_SH);
                    y = (int)((vpk_s[idx >> 5] >> (idx & 31)) & 1u);
                }
                op[(size_t)i * CC] = y ? ev : -ev;
                w = p; h = x;
                // key
                int fj;
                int p2 = g;
                for (;;) {
                    if (p2 < 0) { fj = 0; break; }
                    ull t2r = S[p2];
                    int tk = (int)((t2r >> ks) & IDA);
                    if (tk == IDA) {
                        S[p2] = (t2r & ~((ull)IDA << ks)) | ((ull)j << ks);
                        int f = (int)((t2r >> F_SH) & IDA);
                        p2 = (f == IDA) ? -1 : f;
                    } else {
                        int d = tk;
                        ull recd = S[d];
                        int md = (int)((recd >> M_SH) & IDA);
                        int mp = (int)((t2r >> M_SH) & IDA);
                        if (mp + 1 == md) {
                            fj = d;
                        } else {
                            int bc = j + 1;
                            S[bc] = (recd & ~MMASK) | ((ull)(mp + 1) << M_SH);
                            S[d]  = (recd & ~FMASK) | ((ull)bc << F_SH);
                            fj = bc;
                            u += 1;
                            for (;;) {
                                ull t3 = S[p2];
                                if (((t3 >> ks) & IDA) != (ull)d) break;
                                S[p2] = (t3 & ~((ull)IDA << ks)) | ((ull)bc << ks);
                                int f = (int)((t3 >> F_SH) & IDA);
                                if (f == IDA) break;
                                p2 = f;
                            }
                        }
                        break;
                    }
                }
                int vst = fj;
                while (vst != 0) {
                    ull rc = S[vst];
                    Sr[(vst << 2) | 3] = rv;
                    int f = (int)((rc >> F_SH) & IDA);
                    if (f == IDA) break;
                    vst = f;
                }
                S[j] = (ull)IDA | ((ull)IDA << 12)
                     | ((ull)fj << F_SH)
                     | ((ull)(i + 1) << M_SH) | rvR;
                g = j;
                u += 1;
            }
            __syncwarp();
        }
    }
}

extern "C" void kernel_launch(void* const* d_in, const int* in_sizes, int n_in,
                              void* d_out, int out_size) {
    const float* q = (const float*)d_in[0];
    const float* k = (const float*)d_in[1];
    const float* v = (const float*)d_in[2];
    const float* e = (const float*)d_in[3];
    float* out = (float*)d_out;

    dim3 pg(WPB, BB);
    samx_pack_kernel<<<pg, CC>>>(q, k, v);

    size_t smem = (size_t)RPB * STATES * sizeof(ull)
                + (size_t)RPB * WPB * sizeof(uint32_t)
                + (size_t)RPB * CAPC * sizeof(unsigned short);  // 231644
    cudaFuncSetAttribute(samx_sam_kernel,
                         cudaFuncAttributeMaxDynamicSharedMemorySize, (int)smem);
    int blocks = (NROWS + RPB - 1) / RPB;                 // 147
    samx_sam_kernel<<<blocks, 32 * RPB, smem>>>(e, out);
}

// round 15
// speedup vs baseline: 1.1999x; 1.1999x over previous
#include <cuda_runtime.h>
#include <stdint.h>

// samx_qkv_1bit: suffix-automaton retrieval, 1024 independent serial rows.
// R15 = R13 (warp-specialized query/key pairs, named pair barriers) + the
//   bootstrap fix: qw/kw must be preloaded with word 0 BEFORE the i=1 loop
//   (R13/R14 left them 0 until i=32 -> steps 1..31 used wrong symbols; the
//   bit-identical rel_err across barrier types proved it deterministic).
//   Named pair barriers retained: bar.sync is a full smem fence among
//   participants (anti-dependence direction included).
// smem/block: 229376 (records) + 1792 (vpk) + 476 (NCid) = 231644 <= 232448.

#define BB 4
#define TT 2048
#define CC 256
#define NROWS (BB*CC)          // 1024
#define WPB (TT/32)            // 64 packed words per row
#define STATES 4096            // SAM has <= 2n-1 = 4095 states
#define RPB 7                  // rows per block (2 warps each)
#define CAPC 34                // NCid slots per warp

typedef unsigned long long ull;
#define IDA 0xFFF              // 12-bit absent / -1 marker
#define F_SH 24
#define M_SH 36
#define R_SH 48
#define FULLM 0xFFFFFFFFu
#define RMASK (0xFFFFull << R_SH)
#define MMASK ((ull)IDA << M_SH)
#define FMASK ((ull)IDA << F_SH)

#define PAIR_BAR() asm volatile("bar.sync %0, 64;" :: "r"(pair + 1) : "memory")

__device__ uint32_t g_qpack[NROWS*WPB];
__device__ uint32_t g_kpack[NROWS*WPB];
__device__ uint32_t g_vpack[NROWS*WPB];

// ---------------------------------------------------------------------------
__global__ void samx_pack_kernel(const float* __restrict__ q,
                                 const float* __restrict__ k,
                                 const float* __restrict__ v) {
    int c  = threadIdx.x;
    int wi = blockIdx.x;
    int b  = blockIdx.y;
    int row = b * CC + c;
    size_t base = ((size_t)b * TT + (size_t)wi * 32) * CC + c;
    uint32_t qw = 0, kw = 0, vw = 0;
#pragma unroll
    for (int s = 0; s < 32; s++) {
        if (q[base + (size_t)s * CC] > 0.f) qw |= 1u << s;
        if (k[base + (size_t)s * CC] > 0.f) kw |= 1u << s;
        if (v[base + (size_t)s * CC] > 0.f) vw |= 1u << s;
    }
    g_qpack[row * WPB + wi] = qw;
    g_kpack[row * WPB + wi] = kw;
    g_vpack[row * WPB + wi] = vw;
}

// ---------------------------------------------------------------------------
extern "C" __global__ void __launch_bounds__(64*RPB, 1)
samx_sam_kernel(const float* __restrict__ e, float* __restrict__ out) {
    extern __shared__ ull smem[];
    int warp = threadIdx.x >> 5;
    int lane = threadIdx.x & 31;
    int pair = warp >> 1;              // row within block
    int role = warp & 1;               // 0 = key warp, 1 = query warp
    int row  = blockIdx.x * RPB + pair;
    bool active = (row < NROWS);

    ull* S = smem + (size_t)pair * STATES;
    uint32_t* S32 = (uint32_t*)S;                         // low word = idx 2n
    unsigned short* Sr = (unsigned short*)S;              // r+1 halfword = idx 4n+3
    uint32_t* vpk_s = (uint32_t*)(smem + (size_t)RPB * STATES) + pair * WPB;
    unsigned short* NC = (unsigned short*)((char*)smem
                       + (size_t)RPB * STATES * sizeof(ull)
                       + (size_t)RPB * WPB * sizeof(uint32_t))
                       + pair * CAPC;

    // pair-cooperative vpk copy: 64 words, one per thread of the pair
    if (active) {
        int widx = role * 32 + lane;
        vpk_s[widx] = g_vpack[row * WPB + widx];
    }

    // ---- bootstrap (key warp lane 0 builds step i=0 state) ----
    if (active && role == 0 && lane == 0) {
        uint32_t kw0 = g_kpack[row * WPB];
        int k0 = (kw0 & 1) ? 12 : 0;
        ull rootP = ((ull)IDA | ((ull)IDA << 12) | ((ull)IDA << F_SH));
        rootP = (rootP & ~((ull)IDA << k0)) | ((ull)1 << k0);   // tk[root]=1
        S[0] = rootP;
        S[1] = (ull)IDA | ((ull)IDA << 12) | ((ull)1 << M_SH) | ((ull)1 << R_SH);
        NC[0] = 1; NC[1] = 0;
    }
    __syncthreads();
    if (!active) return;

    if (role == 1) {
        // ====================== QUERY WARP ======================
        const uint32_t* qpk = g_qpack + row * WPB;
        int b = row >> 8;
        int c = row & (CC - 1);
        float ev = e[c];
        float* op = out + (size_t)b * TT * CC + c;
        if (lane == 0) op[0] = -ev;                        // query(0): y=0

        int w = 0, h = 0;
        uint32_t qw = qpk[0];                              // FIX: word 0 preload
        for (int i = 1; i < TT; i++) {
            if ((i & 31) == 0) qw = qpk[i >> 5];           // uniform load
            int qs = ((qw >> (i & 31)) & 1) ? 12 : 0;

            int p = w, x = h;
            for (;;) {
                if (p < 0) { p = 0; x = 0; break; }
                ull r2 = S[p];
                int tq = (int)((r2 >> qs) & IDA);
                if (tq != IDA) { p = tq; x += 1; break; }
                int mq = (int)((r2 >> M_SH) & IDA);
                if (x > mq) x = mq;
                int f = (int)((r2 >> F_SH) & IDA);
                p = (f == IDA) ? -1 : f;
            }
            int y = 0;
            if (x > 0) {
                ull recv = S[p];
                for (;;) {
                    int f = (int)((recv >> F_SH) & IDA);
                    if (f == IDA) break;
                    ull recf = S[f];
                    if ((int)((recf >> M_SH) & IDA) >= x) recv = recf;
                    else break;
                }
                int idx = (int)(recv >> R_SH);             // r+1
                y = (int)((vpk_s[idx >> 5] >> (idx & 31)) & 1u);
            }
            if (lane == 0) op[(size_t)i * CC] = y ? ev : -ev;
            w = p; h = x;

            PAIR_BAR();    // A: query reads done
            PAIR_BAR();    // B: key stores visible
        }
    } else {
        // ======================= KEY WARP =======================
        const uint32_t* kpk = g_kpack + row * WPB;
        int L = 2, g = 1, u = 2;
        bool degraded = false;
        uint32_t kw = kpk[0];                              // FIX: word 0 preload

        for (int i = 1; i < TT; i++) {
            if ((i & 31) == 0) kw = kpk[i >> 5];           // uniform load
            int ks = ((kw >> (i & 31)) & 1) ? 12 : 0;
            int j = u;
            ull rvR = ((ull)(i + 1)) << R_SH;
            unsigned short rv = (unsigned short)(i + 1);

            if (!degraded) {
                // ---- collective compute phase (reads only) ----
                int idt = (int)NC[lane] & IDA;
                ull rec = S[idt];
                bool validt = (lane < L);
                int tkt = validt ? (int)((rec >> ks) & IDA) : IDA;
                int mpt = (int)((rec >> M_SH) & IDA);
                ull planted = (rec & ~((ull)IDA << ks)) | ((ull)j << ks);
                unsigned pres = __ballot_sync(FULLM, tkt != IDA);
                int s = pres ? (__ffs(pres) - 1) : L;
                int d  = __shfl_sync(FULLM, tkt, s & 31);
                int mp = __shfl_sync(FULLM, mpt, s & 31);
                bool hitd = validt && (tkt == d);
                bool inrun = (lane > s) && hitd;
                int bc = j + 1;
                int tgt_nc = tkt;
                int tgt_cl = inrun ? bc : tkt;
                if (lane == s) tgt_cl = bc;
                int pnc = __shfl_up_sync(FULLM, tgt_nc, 1);
                int pcl = __shfl_up_sync(FULLM, tgt_cl, 1);
                bool rng = validt && (lane > s);
                unsigned km_nc = __ballot_sync(FULLM, rng && (tgt_nc != pnc));
                unsigned km_cl = __ballot_sync(FULLM, rng && (tgt_cl != pcl));
                unsigned dch = __ballot_sync(FULLM, validt && (lane < s) && (idt == d));
                bool donchain = pres && (dch != 0);
                int dlane = (__ffs(dch) - 1) & 31;
                ull recd_l = S[pres ? d : 0];
                ull plsh = __shfl_sync(FULLM, planted, dlane);
                ull recd = donchain ? plsh : recd_l;
                int md = (int)((recd >> M_SH) & IDA);
                bool clone = pres && (mp + 1 != md);
                int fj = pres ? (clone ? bc : d) : 0;
                unsigned keepm = clone ? km_cl : km_nc;
                int tgt = clone ? tgt_cl : tgt_nc;
                int nk = __popc(keepm);
                bool keep = (keepm >> lane) & 1u;
                int pos = 2 + __popc(keepm & ((1u << lane) - 1u));
                int Lnext = pres ? nk + 3 : 2;
                ull jrec = (ull)IDA | ((ull)IDA << 12) | ((ull)fj << F_SH)
                         | ((ull)(i + 1) << M_SH) | rvR;
                ull fjrec = (recd & ~(MMASK | RMASK))
                          | ((ull)(mp + 1) << M_SH) | rvR;   // used iff clone

                PAIR_BAR();    // A: query reads done & compute done

                // ---- store phase (single writer per address) ----
                if (lane < s) {
                    if (donchain && lane == dlane) {
                        ull pl = planted;
                        if (clone) pl = (pl & ~FMASK) | ((ull)bc << F_SH);
                        else       pl = (pl & ~RMASK) | rvR;
                        S[idt] = pl;
                    } else {
                        S32[idt << 1] = (uint32_t)planted;   // STS.32 low word
                    }
                }
                if (pres && lane == s) {
                    if (clone) {
                        S32[idt << 1] = (uint32_t)
                            ((rec & ~((ull)IDA << ks)) | ((ull)bc << ks));
                        S[bc] = fjrec;
                        if (!donchain) S[d] = (recd & ~FMASK) | ((ull)bc << F_SH);
                    } else if (!donchain) {
                        Sr[(d << 2) | 3] = rv;
                    }
                }
                if (clone && inrun)
                    S32[idt << 1] = (uint32_t)
                        ((rec & ~((ull)IDA << ks)) | ((ull)bc << ks));
                if (rng) Sr[(tgt << 2) | 3] = rv;            // r-propagation
                if (lane == 0) {
                    S[j] = jrec;
                    NC[0] = (unsigned short)j;
                    NC[1] = (unsigned short)fj;
                    NC[Lnext - 1] = 0;                       // root terminal
                }
                if (keep) NC[pos] = (unsigned short)tgt;

                PAIR_BAR();    // B: stores visible

                g = j; u += clone ? 2 : 1; L = Lnext;
                if (L > 32) degraded = true;
            } else {
                PAIR_BAR();    // A: wait for query reads before serial writes
                if (lane == 0) {
                    int fj;
                    int p2 = g;
                    for (;;) {
                        if (p2 < 0) { fj = 0; break; }
                        ull t2r = S[p2];
                        int tk = (int)((t2r >> ks) & IDA);
                        if (tk == IDA) {
                            S[p2] = (t2r & ~((ull)IDA << ks)) | ((ull)j << ks);
                            int f = (int)((t2r >> F_SH) & IDA);
                            p2 = (f == IDA) ? -1 : f;
                        } else {
                            int d = tk;
                            ull recd = S[d];
                            int md = (int)((recd >> M_SH) & IDA);
                            int mp = (int)((t2r >> M_SH) & IDA);
                            if (mp + 1 == md) {
                                fj = d;
                            } else {
                                int bc = j + 1;
                                S[bc] = (recd & ~MMASK) | ((ull)(mp + 1) << M_SH);
                                S[d]  = (recd & ~FMASK) | ((ull)bc << F_SH);
                                fj = bc;
                                u += 1;
                                for (;;) {
                                    ull t3 = S[p2];
                                    if (((t3 >> ks) & IDA) != (ull)d) break;
                                    S[p2] = (t3 & ~((ull)IDA << ks)) | ((ull)bc << ks);
                                    int f = (int)((t3 >> F_SH) & IDA);
                                    if (f == IDA) break;
                                    p2 = f;
                                }
                            }
                            break;
                        }
                    }
                    int vst = fj;
                    while (vst != 0) {
                        ull rc = S[vst];
                        Sr[(vst << 2) | 3] = rv;
                        int f = (int)((rc >> F_SH) & IDA);
                        if (f == IDA) break;
                        vst = f;
                    }
                    S[j] = (ull)IDA | ((ull)IDA << 12)
                         | ((ull)fj << F_SH)
                         | ((ull)(i + 1) << M_SH) | rvR;
                    g = j;
                    u += 1;
                }
                g = __shfl_sync(FULLM, g, 0);
                u = __shfl_sync(FULLM, u, 0);
                PAIR_BAR();    // B: stores visible
            }
        }
    }
}

extern "C" void kernel_launch(void* const* d_in, const int* in_sizes, int n_in,
                              void* d_out, int out_size) {
    const float* q = (const float*)d_in[0];
    const float* k = (const float*)d_in[1];
    const float* v = (const float*)d_in[2];
    const float* e = (const float*)d_in[3];
    float* out = (float*)d_out;

    dim3 pg(WPB, BB);
    samx_pack_kernel<<<pg, CC>>>(q, k, v);

    size_t smem = (size_t)RPB * STATES * sizeof(ull)
                + (size_t)RPB * WPB * sizeof(uint32_t)
                + (size_t)RPB * CAPC * sizeof(unsigned short);  // 231644
    cudaFuncSetAttribute(samx_sam_kernel,
                         cudaFuncAttributeMaxDynamicSharedMemorySize, (int)smem);
    int blocks = (NROWS + RPB - 1) / RPB;                 // 147
    samx_sam_kernel<<<blocks, 64 * RPB, smem>>>(e, out);
}